// round 10
// baseline (speedup 1.0000x reference)
#include <cuda_runtime.h>
#include <math.h>
#include <float.h>

#define OUTD    12
#define N_VOX   1728              // 12*12*12
#define N_ROIS  128
#define N_PTS   160000
#define NCH     64
#define KMAX    64                // cap on points per (roi,voxel); fallback handles overflow
#define NRV     (N_ROIS * N_VOX)  // 221184
#define NF4     (NRV * NCH / 4)   // 3,538,944 float4s in output

#define POOL_BLOCKS 888
#define POOL_WARPS  (POOL_BLOCKS * 8)

static_assert(N_PTS % 256 == 0, "exact build grid");

// Scratch (__device__ globals = sanctioned scratch; zero-initialized at load).
// Invariants restored every run: d_count zeroed per-entry by pool, d_qn/d_done
// reset by the last pool block out.
__device__ int d_count[NRV];
__device__ __align__(16) int d_list[NRV * KMAX];   // 16B align for int4 loads
__device__ int d_qn;
__device__ int d_done;
__device__ int d_queue[NRV];

// ---------------------------------------------------------------------------
// Kernel 1: merged zero-fill + list build (R5 structure — measured best).
// Fire-and-forget STG.128 zero-fill drains under the ROI loop's pure-issue
// compute. One thread per point, warp-uniform loop over all 128 ROIs with
// smem-staged params (broadcast LDS.128) and circle quick-reject. The unique
// first inserter of each voxel pushes rv onto the global worklist.
// ---------------------------------------------------------------------------
__global__ __launch_bounds__(256) void build_fill_kernel(
    const float* __restrict__ rois, const float* __restrict__ pts,
    float* __restrict__ out)
{
    __shared__ float4 sA[N_ROIS];  // {cx, cy, r2_margin, cz}
    __shared__ float4 sB[N_ROIS];  // {cosa, sina, hdx, hdy}
    __shared__ float4 sC[N_ROIS];  // {hdz, vx, vy, vz}

    int t = threadIdx.x;
    int p = blockIdx.x * blockDim.x + t;      // always < N_PTS (exact grid)

    // Point load issued early.
    float px = pts[3 * p + 0];
    float py = pts[3 * p + 1];
    float pz = pts[3 * p + 2];

    if (t < N_ROIS) {
        const float* R = rois + t * 7;
        float cx = R[0], cy = R[1], cz = R[2];
        float dx = R[3], dy = R[4], dz = R[5];
        float ry = R[6];
        float hdx = dx * 0.5f, hdy = dy * 0.5f, hdz = dz * 0.5f;
        float r2  = (hdx * hdx + hdy * hdy) * 1.0002f + 1e-6f;  // conservative
        float ca  = cosf(-ry), sa = sinf(-ry);
        sA[t] = make_float4(cx, cy, r2, cz);
        sB[t] = make_float4(ca, sa, hdx, hdy);
        sC[t] = make_float4(hdz, dx / (float)OUTD, dy / (float)OUTD, dz / (float)OUTD);
    }

    // Zero-fill whole output: ~22 coalesced fire-and-forget STG.128/thread,
    // streaming to limit L2 pollution of d_count/d_list.
    {
        float4 z = make_float4(0.f, 0.f, 0.f, 0.f);
        float4* o4 = (float4*)out;
        for (int i = p; i < NF4; i += N_PTS) __stcs(&o4[i], z);
    }
    __syncthreads();

    #pragma unroll 4
    for (int r = 0; r < N_ROIS; r++) {
        float4 A = sA[r];                     // broadcast LDS.128 (uniform r)
        float sx = px - A.x;
        float sy = py - A.y;
        float d2 = sx * sx + sy * sy;
        if (d2 > A.z) continue;               // ~99.8% rejected here

        float sz = pz - A.w;
        float4 B = sB[r];
        float4 C = sC[r];
        float lx = sx * B.x - sy * B.y;       // rotate into roi frame (angle = -ry)
        float ly = sx * B.y + sy * B.x;
        bool in_box = (lx > -B.z) && (lx < B.z) &&
                      (ly > -B.w) && (ly < B.w) &&
                      (fabsf(sz - C.x) <= C.x);
        if (!in_box) continue;

        int xi = min(OUTD - 1, max(0, (int)floorf((lx + B.z) / C.y)));
        int yi = min(OUTD - 1, max(0, (int)floorf((ly + B.w) / C.z)));
        int zi = min(OUTD - 1, max(0, (int)floorf(sz / C.w)));
        int rv = r * N_VOX + xi * (OUTD * OUTD) + yi * OUTD + zi;
        int c = atomicAdd(&d_count[rv], 1);
        if (c < KMAX) d_list[rv * KMAX + c] = p;
        if (c == 0) {                         // unique first inserter
            int qi = atomicAdd(&d_qn, 1);
            d_queue[qi] = rv;
        }
    }
}

// ---------------------------------------------------------------------------
// Kernel 2: worklist pool. Warps grid-stride the ~17K queue entries
// (~2.4/warp). Per entry: (count, pid int4) -> up to 4 independent feature
// rows -> 256B output store; 2-deep pipeline prefetches the next entry's
// chain. Counts self-cleaned per entry; the LAST BLOCK OUT (ticket counter)
// resets d_qn/d_done -> all invariants restored race-free for next replay.
// ---------------------------------------------------------------------------
__global__ __launch_bounds__(256, 6) void pool_kernel(
    const float* __restrict__ rois, const float* __restrict__ pts,
    const float* __restrict__ feat, float* __restrict__ out)
{
    int lane  = threadIdx.x & 31;
    int gwarp = blockIdx.x * 8 + (threadIdx.x >> 5);
    int qn    = d_qn;                          // uniform read

    int i = gwarp;
    int nRv = -1, nN = 0;
    int4 nP4 = make_int4(0, 0, 0, 0);
    if (i < qn) {
        nRv = d_queue[i];
        nN  = d_count[nRv];
        nP4 = *(const int4*)&d_list[(size_t)nRv * KMAX];
    }

    while (nRv >= 0) {
        int rv = nRv, n = nN;
        int4 p4 = nP4;
        if (lane == 0) d_count[rv] = 0;        // self-clean for next replay
        i += POOL_WARPS;
        if (i < qn) {
            nRv = d_queue[i];
            nN  = d_count[nRv];
            nP4 = *(const int4*)&d_list[(size_t)nRv * KMAX];   // prefetch next
        } else {
            nRv = -1;
        }

        float mx0 = -FLT_MAX, mx1 = -FLT_MAX;
        int mm = min(n, KMAX);
        {   // up to 4 independent feature-row loads (MLP), predicated
            float2 v0, v1, v2, v3;
            if (mm > 0) v0 = ((const float2*)(feat + (size_t)p4.x * NCH))[lane];
            if (mm > 1) v1 = ((const float2*)(feat + (size_t)p4.y * NCH))[lane];
            if (mm > 2) v2 = ((const float2*)(feat + (size_t)p4.z * NCH))[lane];
            if (mm > 3) v3 = ((const float2*)(feat + (size_t)p4.w * NCH))[lane];
            if (mm > 0) { mx0 = fmaxf(mx0, v0.x); mx1 = fmaxf(mx1, v0.y); }
            if (mm > 1) { mx0 = fmaxf(mx0, v1.x); mx1 = fmaxf(mx1, v1.y); }
            if (mm > 2) { mx0 = fmaxf(mx0, v2.x); mx1 = fmaxf(mx1, v2.y); }
            if (mm > 3) { mx0 = fmaxf(mx0, v3.x); mx1 = fmaxf(mx1, v3.y); }
        }
        const int* lst = &d_list[(size_t)rv * KMAX];
        for (int j = 4; j < mm; j++) {         // rare (P(n>4) tiny)
            int pid = lst[j];
            float2 v = ((const float2*)(feat + (size_t)pid * NCH))[lane];
            mx0 = fmaxf(mx0, v.x);
            mx1 = fmaxf(mx1, v.y);
        }

        if (n > KMAX) {
            // Correctness fallback (statistically never taken): rescan all
            // points. n is warp-uniform so the whole warp enters together.
            int r = rv / N_VOX, vox = rv % N_VOX;
            int xi = vox / (OUTD * OUTD), yi = (vox / OUTD) % OUTD, zi = vox % OUTD;
            const float* R = rois + r * 7;
            float cx = R[0], cy = R[1], cz = R[2];
            float dx = R[3], dy = R[4], dz = R[5];
            float ry = R[6];
            float hdx = dx * 0.5f, hdy = dy * 0.5f, hdz = dz * 0.5f;
            float ca = cosf(-ry), sa = sinf(-ry);
            float vx = dx / (float)OUTD, vy = dy / (float)OUTD, vz = dz / (float)OUTD;
            for (int bb = 0; bb < N_PTS; bb += 32) {
                int pp = bb + lane;
                bool hit = false;
                {
                    float sx = pts[3 * pp + 0] - cx;
                    float sy = pts[3 * pp + 1] - cy;
                    float szz = pts[3 * pp + 2] - cz;
                    float lx = sx * ca - sy * sa;
                    float ly = sx * sa + sy * ca;
                    if ((lx > -hdx) && (lx < hdx) && (ly > -hdy) && (ly < hdy) &&
                        (fabsf(szz - hdz) <= hdz)) {
                        int xa = min(OUTD - 1, max(0, (int)floorf((lx + hdx) / vx)));
                        int ya = min(OUTD - 1, max(0, (int)floorf((ly + hdy) / vy)));
                        int za = min(OUTD - 1, max(0, (int)floorf(szz / vz)));
                        hit = (xa == xi) && (ya == yi) && (za == zi);
                    }
                }
                unsigned mk = __ballot_sync(0xffffffffu, hit);
                while (mk) {
                    int src = __ffs(mk) - 1;
                    mk &= mk - 1;
                    int pid = bb + src;
                    float2 v = ((const float2*)(feat + (size_t)pid * NCH))[lane];
                    mx0 = fmaxf(mx0, v.x);
                    mx1 = fmaxf(mx1, v.y);
                }
            }
        }

        float2* o = (float2*)(out + (size_t)rv * NCH);
        __stcs(&o[lane], make_float2(mx0, mx1));
    }

    // Last block out resets the worklist counter (race-free across any
    // scheduling order; ticket counter + threadfence).
    __syncthreads();
    if (threadIdx.x == 0) {
        __threadfence();
        int ticket = atomicAdd(&d_done, 1);
        if (ticket == POOL_BLOCKS - 1) {
            d_qn = 0;
            d_done = 0;
        }
    }
}

// ---------------------------------------------------------------------------
extern "C" void kernel_launch(void* const* d_in, const int* in_sizes, int n_in,
                              void* d_out, int out_size)
{
    const float* rois = (const float*)d_in[0];       // (128, 7)
    const float* pts  = (const float*)d_in[1];       // (160000, 3)
    const float* feat = (const float*)d_in[2];       // (160000, 64)
    float* out = (float*)d_out;                      // (128, 12, 12, 12, 64)

    build_fill_kernel<<<N_PTS / 256, 256>>>(rois, pts, out); // zeros + lists + worklist
    pool_kernel<<<POOL_BLOCKS, 256>>>(rois, pts, feat, out); // worklist gather
}